// round 2
// baseline (speedup 1.0000x reference)
#include <cuda_runtime.h>

#define B_  32
#define C_  64
#define H_  128
#define W_  128
#define HW  16384            // H_*W_
#define CR  38               // floor(0.6*64)=38, even -> C_r=38
#define CIR 26               // 64-38
#define NBC 8                // batches per chunk
#define NCHUNK (B_ / NBC)    // 4

// Scratch (allocation-free rule: __device__ globals)
__device__ unsigned long long g_mask[B_];
__device__ float4 g_maps[B_ * HW];     // {ravg, rmax, iravg, irmax} per pixel, 8 MB
__device__ float  g_A1  [B_ * HW];     // 2 MB
__device__ float  g_A2  [B_ * HW];     // 2 MB

// ---------------------------------------------------------------------------
// Kernel 1: per-batch relevance bitmask from top-k(CR) of M[b, :]
// rank(c) = #{j : M[j] > M[c]} + #{j < c : M[j] == M[c]}  (jax top_k tiebreak)
// ---------------------------------------------------------------------------
__global__ void mask_kernel(const float* __restrict__ M) {
    int b = blockIdx.x;
    int c = threadIdx.x;
    __shared__ float m[C_];
    __shared__ unsigned long long sm;
    if (c == 0) sm = 0ull;
    m[c] = M[b * C_ + c];
    __syncthreads();
    float v = m[c];
    int rank = 0;
    #pragma unroll
    for (int j = 0; j < C_; j++) {
        float mj = m[j];
        rank += (mj > v) || (mj == v && j < c);
    }
    if (rank < CR) atomicOr(&sm, 1ull << c);
    __syncthreads();
    if (c == 0) g_mask[b] = sm;
}

// ---------------------------------------------------------------------------
// Kernel 2 (per chunk): channel reductions, float4 over 4 consecutive pixels.
// relevant = mask*x has exact zeros on masked-out channels, so the channel
// max always includes 0 -> max accumulators init to 0.
// Writes packed float4 maps {ravg, rmax, iravg, irmax}.
// ---------------------------------------------------------------------------
__global__ void reduce_kernel(const float* __restrict__ x, int b0) {
    int t  = blockIdx.x * blockDim.x + threadIdx.x;   // 0 .. NBC*4096-1
    int b  = b0 + (t >> 12);
    int pg = t & 4095;                                 // pixel-group (4 px)

    unsigned long long mask = g_mask[b];
    const float4* xb = (const float4*)(x + (size_t)b * C_ * HW) + pg;

    float4 rs = {0,0,0,0}, rm = {0,0,0,0};
    float4 is = {0,0,0,0}, im = {0,0,0,0};

    #pragma unroll
    for (int c = 0; c < C_; c++) {
        float4 v = __ldg(xb + c * (HW / 4));
        if ((mask >> c) & 1ull) {
            rs.x += v.x; rs.y += v.y; rs.z += v.z; rs.w += v.w;
            rm.x = fmaxf(rm.x, v.x); rm.y = fmaxf(rm.y, v.y);
            rm.z = fmaxf(rm.z, v.z); rm.w = fmaxf(rm.w, v.w);
        } else {
            is.x += v.x; is.y += v.y; is.z += v.z; is.w += v.w;
            im.x = fmaxf(im.x, v.x); im.y = fmaxf(im.y, v.y);
            im.z = fmaxf(im.z, v.z); im.w = fmaxf(im.w, v.w);
        }
    }

    const float kr = 1.0f / (float)CR, ki = 1.0f / (float)CIR;
    float4* mp = g_maps + (size_t)b * HW + pg * 4;
    mp[0] = make_float4(rs.x * kr, rm.x, is.x * ki, im.x);
    mp[1] = make_float4(rs.y * kr, rm.y, is.y * ki, im.y);
    mp[2] = make_float4(rs.z * kr, rm.z, is.z * ki, im.z);
    mp[3] = make_float4(rs.w * kr, rm.w, is.w * ki, im.w);
}

// ---------------------------------------------------------------------------
// Kernel 3 (per chunk): 7x7 conv (2ch->1), zero pad 3, BN + relu + sigmoid.
// One float4 map load per tap covers both A_S1 and A_S2 inputs.
// ---------------------------------------------------------------------------
__global__ void conv_kernel(const float* __restrict__ cw,
                            const float* __restrict__ gamma,
                            const float* __restrict__ beta,
                            const float* __restrict__ mean,
                            const float* __restrict__ var,
                            int b0) {
    __shared__ float sw[98];
    if (threadIdx.x < 98) sw[threadIdx.x] = cw[threadIdx.x];
    __syncthreads();

    int t   = blockIdx.x * blockDim.x + threadIdx.x;  // 0 .. NBC*HW-1
    int b   = b0 + (t >> 14);
    int pix = t & (HW - 1);
    int h = pix >> 7;
    int w = pix & (W_ - 1);

    const float4* mp = g_maps + (size_t)b * HW;

    float y1 = 0.f, y2 = 0.f;
    #pragma unroll
    for (int kh = 0; kh < 7; kh++) {
        int hh = h + kh - 3;
        if (hh < 0 || hh >= H_) continue;
        #pragma unroll
        for (int kw = 0; kw < 7; kw++) {
            int ww = w + kw - 3;
            if (ww < 0 || ww >= W_) continue;
            float4 m = __ldg(mp + hh * W_ + ww);
            float w0 = sw[kh * 7 + kw];
            float w1 = sw[49 + kh * 7 + kw];
            y1 = fmaf(m.x, w0, fmaf(m.y, w1, y1));
            y2 = fmaf(m.z, w0, fmaf(m.w, w1, y2));
        }
    }

    float scale = rsqrtf(var[0] + 1e-5f) * gamma[0];
    float bias  = beta[0] - mean[0] * scale;
    y1 = fmaxf(fmaf(y1, scale, bias), 0.f);
    y2 = fmaxf(fmaf(y2, scale, bias), 0.f);
    int p = b * HW + pix;
    g_A1[p] = 1.0f / (1.0f + expf(-y1));
    g_A2[p] = 1.0f / (1.0f + expf(-y2));
}

// ---------------------------------------------------------------------------
// Kernel 4 (per chunk): out = x * (relevant ? A_S1 : A_S2), float4-vectorized.
// x chunk should be L2-resident from the reduce pass.
// ---------------------------------------------------------------------------
__global__ void combine_kernel(const float* __restrict__ x,
                               float* __restrict__ out, int b0) {
    size_t i = (size_t)blockIdx.x * blockDim.x + threadIdx.x;  // float4 idx in chunk
    size_t e = i << 2;
    int bl   = (int)(e >> 20);          // C_*HW = 2^20
    int b    = b0 + bl;
    int c    = (int)((e >> 14) & 63);
    int pix4 = (int)((e & (HW - 1)) >> 2);

    size_t gi = ((size_t)b0 * C_ * HW >> 2) + i;
    float4 v = ((const float4*)x)[gi];

    bool rel = (g_mask[b] >> c) & 1ull;
    const float4* A4 = (const float4*)(rel ? g_A1 : g_A2);
    float4 a = __ldg(A4 + ((size_t)b * HW >> 2) + pix4);

    float4 r;
    r.x = v.x * a.x;
    r.y = v.y * a.y;
    r.z = v.z * a.z;
    r.w = v.w * a.w;
    ((float4*)out)[gi] = r;
}

// ---------------------------------------------------------------------------
extern "C" void kernel_launch(void* const* d_in, const int* in_sizes, int n_in,
                              void* d_out, int out_size) {
    const float* x     = (const float*)d_in[0];
    const float* M     = (const float*)d_in[1];
    const float* cw    = (const float*)d_in[2];
    const float* gamma = (const float*)d_in[3];
    const float* beta  = (const float*)d_in[4];
    const float* mean  = (const float*)d_in[5];
    const float* var   = (const float*)d_in[6];
    float* out = (float*)d_out;

    mask_kernel<<<B_, C_>>>(M);

    const int RED_T = NBC * HW / 4;           // 32768 threads per chunk
    const int CNV_T = NBC * HW;               // 131072
    const int CMB_T = NBC * C_ * HW / 4;      // 2097152

    for (int ch = 0; ch < NCHUNK; ch++) {
        int b0 = ch * NBC;
        reduce_kernel <<<RED_T / 256, 256>>>(x, b0);
        conv_kernel   <<<CNV_T / 256, 256>>>(cw, gamma, beta, mean, var, b0);
        combine_kernel<<<CMB_T / 256, 256>>>(x, out, b0);
    }
}

// round 3
// speedup vs baseline: 1.2414x; 1.2414x over previous
#include <cuda_runtime.h>

#define B_  32
#define C_  64
#define H_  128
#define W_  128
#define HW  16384            // H_*W_
#define CR  38
#define CIR 26

// fused-kernel tile
#define TW  32               // tile width (pixels)
#define TH  16               // tile height
#define HALO_W (TW + 6)      // 38
#define HALO_H (TH + 6)      // 22

// Scratch (allocation-free rule: __device__ globals)
__device__ unsigned long long g_mask[B_];
__device__ float4 g_maps[B_ * HW];   // {ravg, rmax, iravg, irmax}, 8 MB (L2-resident)

// ---------------------------------------------------------------------------
// Kernel 1: per-batch relevance bitmask from top-k(CR) of M[b, :]
// ---------------------------------------------------------------------------
__global__ void mask_kernel(const float* __restrict__ M) {
    int b = blockIdx.x;
    int c = threadIdx.x;
    __shared__ float m[C_];
    __shared__ unsigned long long sm;
    if (c == 0) sm = 0ull;
    m[c] = M[b * C_ + c];
    __syncthreads();
    float v = m[c];
    int rank = 0;
    #pragma unroll
    for (int j = 0; j < C_; j++) {
        float mj = m[j];
        rank += (mj > v) || (mj == v && j < c);
    }
    if (rank < CR) atomicOr(&sm, 1ull << c);
    __syncthreads();
    if (c == 0) g_mask[b] = sm;
}

// ---------------------------------------------------------------------------
// Kernel 2: channel reductions, float4 over 4 consecutive pixels, full grid.
// masked entries contribute exact zeros -> max accumulators init to 0.
// ---------------------------------------------------------------------------
__global__ void reduce_kernel(const float* __restrict__ x) {
    int t  = blockIdx.x * blockDim.x + threadIdx.x;   // 0 .. B_*4096-1
    int b  = t >> 12;
    int pg = t & 4095;                                 // float4 pixel-group

    unsigned long long mask = g_mask[b];
    const float4* xb = (const float4*)(x + (size_t)b * C_ * HW) + pg;

    float4 rs = {0,0,0,0}, rm = {0,0,0,0};
    float4 is = {0,0,0,0}, im = {0,0,0,0};

    #pragma unroll
    for (int c = 0; c < C_; c++) {
        float4 v = __ldg(xb + c * (HW / 4));
        if ((mask >> c) & 1ull) {
            rs.x += v.x; rs.y += v.y; rs.z += v.z; rs.w += v.w;
            rm.x = fmaxf(rm.x, v.x); rm.y = fmaxf(rm.y, v.y);
            rm.z = fmaxf(rm.z, v.z); rm.w = fmaxf(rm.w, v.w);
        } else {
            is.x += v.x; is.y += v.y; is.z += v.z; is.w += v.w;
            im.x = fmaxf(im.x, v.x); im.y = fmaxf(im.y, v.y);
            im.z = fmaxf(im.z, v.z); im.w = fmaxf(im.w, v.w);
        }
    }

    const float kr = 1.0f / (float)CR, ki = 1.0f / (float)CIR;
    float4* mp = g_maps + (size_t)b * HW + pg * 4;
    mp[0] = make_float4(rs.x * kr, rm.x, is.x * ki, im.x);
    mp[1] = make_float4(rs.y * kr, rm.y, is.y * ki, im.y);
    mp[2] = make_float4(rs.z * kr, rm.z, is.z * ki, im.z);
    mp[3] = make_float4(rs.w * kr, rm.w, is.w * ki, im.w);
}

// ---------------------------------------------------------------------------
// Kernel 3: fused conv(7x7, zero-pad-3) + BN + relu + sigmoid + combine.
// One CTA = one 32x16 pixel tile of one batch. A1/A2 stay in registers;
// each thread owns pixels (h, w) and (h+8, w), h=t/32, w=t%32.
// ---------------------------------------------------------------------------
__global__ void __launch_bounds__(256) fused_kernel(
        const float* __restrict__ x,
        float* __restrict__ out,
        const float* __restrict__ cw,
        const float* __restrict__ gamma,
        const float* __restrict__ beta,
        const float* __restrict__ mean,
        const float* __restrict__ var) {
    __shared__ float4 smaps[HALO_H][HALO_W];
    __shared__ float sw[98];

    int t = threadIdx.x;
    int tile = blockIdx.x;                 // 0 .. 1023
    int b  = tile >> 5;                    // 32 tiles per batch
    int tid2 = tile & 31;
    int h0 = (tid2 >> 2) * TH;             // 8 tile-rows
    int w0 = (tid2 & 3) * TW;              // 4 tile-cols

    if (t < 98) sw[t] = cw[t];

    // --- halo load: 22 x 38 float4 (zero outside image) ---
    const float4* mb = g_maps + (size_t)b * HW;
    for (int i = t; i < HALO_H * HALO_W; i += 256) {
        int r  = i / HALO_W;
        int cx = i - r * HALO_W;
        int gh = h0 + r - 3;
        int gw = w0 + cx - 3;
        float4 v = {0,0,0,0};
        if (gh >= 0 && gh < H_ && gw >= 0 && gw < W_)
            v = __ldg(mb + gh * W_ + gw);
        smaps[r][cx] = v;
    }
    __syncthreads();

    // --- conv + BN + relu + sigmoid for 2 pixels per thread ---
    int h = t >> 5;          // 0..7
    int w = t & 31;          // 0..31
    // pixel A: (h, w); pixel B: (h+8, w)  [local coords]
    float y11 = 0.f, y12 = 0.f, y21 = 0.f, y22 = 0.f;
    #pragma unroll
    for (int kh = 0; kh < 7; kh++) {
        #pragma unroll
        for (int kw = 0; kw < 7; kw++) {
            float w0c = sw[kh * 7 + kw];
            float w1c = sw[49 + kh * 7 + kw];
            float4 m1 = smaps[h + kh][w + kw];
            float4 m2 = smaps[h + 8 + kh][w + kw];
            y11 = fmaf(m1.x, w0c, fmaf(m1.y, w1c, y11));
            y12 = fmaf(m1.z, w0c, fmaf(m1.w, w1c, y12));
            y21 = fmaf(m2.x, w0c, fmaf(m2.y, w1c, y21));
            y22 = fmaf(m2.z, w0c, fmaf(m2.w, w1c, y22));
        }
    }

    float scale = rsqrtf(var[0] + 1e-5f) * gamma[0];
    float bias  = beta[0] - mean[0] * scale;
    y11 = fmaxf(fmaf(y11, scale, bias), 0.f);
    y12 = fmaxf(fmaf(y12, scale, bias), 0.f);
    y21 = fmaxf(fmaf(y21, scale, bias), 0.f);
    y22 = fmaxf(fmaf(y22, scale, bias), 0.f);
    float a11 = 1.0f / (1.0f + expf(-y11));   // pixel A, relevant
    float a12 = 1.0f / (1.0f + expf(-y12));   // pixel A, irrelevant
    float a21 = 1.0f / (1.0f + expf(-y21));   // pixel B, relevant
    float a22 = 1.0f / (1.0f + expf(-y22));   // pixel B, irrelevant

    // --- channel loop: out = x * (rel ? A1 : A2) ---
    unsigned long long mask = g_mask[b];
    size_t base = (size_t)b * C_ * HW + (h0 + h) * W_ + (w0 + w);
    const float* xp = x + base;
    float* op = out + base;
    const int d2 = 8 * W_;   // pixel B offset

    #pragma unroll 8
    for (int c = 0; c < C_; c++) {
        bool rel = (mask >> c) & 1ull;
        float fA = rel ? a11 : a12;
        float fB = rel ? a21 : a22;
        size_t o = (size_t)c * HW;
        float v1 = __ldg(xp + o);
        float v2 = __ldg(xp + o + d2);
        op[o]      = v1 * fA;
        op[o + d2] = v2 * fB;
    }
}

// ---------------------------------------------------------------------------
extern "C" void kernel_launch(void* const* d_in, const int* in_sizes, int n_in,
                              void* d_out, int out_size) {
    const float* x     = (const float*)d_in[0];
    const float* M     = (const float*)d_in[1];
    const float* cw    = (const float*)d_in[2];
    const float* gamma = (const float*)d_in[3];
    const float* beta  = (const float*)d_in[4];
    const float* mean  = (const float*)d_in[5];
    const float* var   = (const float*)d_in[6];
    float* out = (float*)d_out;

    mask_kernel<<<B_, C_>>>(M);

    const int RED_T = B_ * HW / 4;            // 131072 threads
    reduce_kernel<<<RED_T / 256, 256>>>(x);

    const int NTILES = B_ * (H_ / TH) * (W_ / TW);   // 32*8*4 = 1024
    fused_kernel<<<NTILES, 256>>>(x, out, cw, gamma, beta, mean, var);
}

// round 4
// speedup vs baseline: 1.4982x; 1.2069x over previous
#include <cuda_runtime.h>

#define B_  32
#define C_  64
#define H_  128
#define W_  128
#define HW  16384            // H_*W_
#define CR  38               // floor(0.6*64)=38, even
#define CIR 26

// fused tile: 64 px wide (16 float4) x 16 rows, 256 threads, 4 px/thread
#define TW4 16               // tile width in float4
#define TH  16

// Scratch (allocation-free rule: __device__ globals)
__device__ unsigned long long g_mask[B_];
__device__ float4 g_maps[B_ * HW];   // {ravg, rmax, iravg, irmax}, 8 MB

// ---------------------------------------------------------------------------
// rank-based top-k mask for batch b, computed cooperatively by threads 0..63.
// rank(c) = #{j : M[j] > M[c]} + #{j < c : M[j] == M[c]}  (jax top_k tiebreak)
// ---------------------------------------------------------------------------
__device__ __forceinline__ unsigned long long
compute_mask(const float* __restrict__ M, int b, int t,
             float* sm, unsigned long long* smask) {
    if (t == 0) *smask = 0ull;
    if (t < C_) sm[t] = __ldg(M + b * C_ + t);
    __syncthreads();
    if (t < C_) {
        float v = sm[t];
        int rank = 0;
        #pragma unroll
        for (int j = 0; j < C_; j++) {
            float mj = sm[j];
            rank += (mj > v) || (mj == v && j < t);
        }
        if (rank < CR) atomicOr(smask, 1ull << t);
    }
    __syncthreads();
    return *smask;
}

// ---------------------------------------------------------------------------
// Kernel 1: mask + channel reductions. 16 CTAs per batch, float4 per thread.
// Masked-out entries are exact zeros in the reference -> max init to 0.
// ---------------------------------------------------------------------------
__global__ void __launch_bounds__(256) reduce_kernel(
        const float* __restrict__ x, const float* __restrict__ M) {
    __shared__ float sm[C_];
    __shared__ unsigned long long smask;

    int t  = threadIdx.x;
    int b  = blockIdx.x >> 4;                       // 16 CTAs per batch
    int pg = (blockIdx.x & 15) * 256 + t;           // float4 pixel-group 0..4095

    unsigned long long mask = compute_mask(M, b, t, sm, &smask);
    if (pg == 0) g_mask[b] = mask;                  // for the fused kernel

    const float4* xb = (const float4*)(x + (size_t)b * C_ * HW) + pg;

    float4 rs = {0,0,0,0}, rm = {0,0,0,0};
    float4 is = {0,0,0,0}, im = {0,0,0,0};

    #pragma unroll
    for (int c = 0; c < C_; c++) {
        float4 v = __ldg(xb + c * (HW / 4));
        if ((mask >> c) & 1ull) {
            rs.x += v.x; rs.y += v.y; rs.z += v.z; rs.w += v.w;
            rm.x = fmaxf(rm.x, v.x); rm.y = fmaxf(rm.y, v.y);
            rm.z = fmaxf(rm.z, v.z); rm.w = fmaxf(rm.w, v.w);
        } else {
            is.x += v.x; is.y += v.y; is.z += v.z; is.w += v.w;
            im.x = fmaxf(im.x, v.x); im.y = fmaxf(im.y, v.y);
            im.z = fmaxf(im.z, v.z); im.w = fmaxf(im.w, v.w);
        }
    }

    const float kr = 1.0f / (float)CR, ki = 1.0f / (float)CIR;
    float4* mp = g_maps + (size_t)b * HW + pg * 4;
    mp[0] = make_float4(rs.x * kr, rm.x, is.x * ki, im.x);
    mp[1] = make_float4(rs.y * kr, rm.y, is.y * ki, im.y);
    mp[2] = make_float4(rs.z * kr, rm.z, is.z * ki, im.z);
    mp[3] = make_float4(rs.w * kr, rm.w, is.w * ki, im.w);
}

// ---------------------------------------------------------------------------
// Kernel 2: fused conv(7x7, pad 3) + BN + relu + sigmoid + combine.
// CTA = 64x16 px tile of one batch; thread = 4 consecutive px (one float4).
// Conv reads map rows straight from global (L1/L2-resident, heavy reuse)
// into a 10-wide register segment per kh row.
// ---------------------------------------------------------------------------
__global__ void __launch_bounds__(256) fused_kernel(
        const float* __restrict__ x,
        float* __restrict__ out,
        const float* __restrict__ cw,
        const float* __restrict__ gamma,
        const float* __restrict__ beta,
        const float* __restrict__ mean,
        const float* __restrict__ var) {
    __shared__ float sw[98];

    int t = threadIdx.x;
    int tile = blockIdx.x;                  // 0..511
    int b  = tile >> 4;                     // 16 tiles per batch
    int ti = tile & 15;
    int h0 = (ti >> 1) * TH;                // 8 tile-rows
    int w0 = (ti & 1) * (TW4 * 4);          // 2 tile-cols (0 or 64)

    if (t < 98) sw[t] = __ldg(cw + t);
    __syncthreads();

    int ty = t >> 4;                        // 0..15
    int tx = t & 15;                        // 0..15
    int h  = h0 + ty;                       // global row of this thread's px
    int wb = w0 + tx * 4;                   // global col of first px

    const float4* mb = g_maps + (size_t)b * HW;

    // conv accumulators for 4 pixels x 2 streams
    float y1[4] = {0,0,0,0}, y2[4] = {0,0,0,0};

    #pragma unroll
    for (int kh = 0; kh < 7; kh++) {
        int gh = h + kh - 3;
        float4 seg[10];
        #pragma unroll
        for (int s = 0; s < 10; s++) {
            int gw = wb + s - 3;
            float4 v = {0,0,0,0};
            if (gh >= 0 && gh < H_ && gw >= 0 && gw < W_)
                v = __ldg(mb + gh * W_ + gw);
            seg[s] = v;
        }
        #pragma unroll
        for (int kw = 0; kw < 7; kw++) {
            float w0c = sw[kh * 7 + kw];
            float w1c = sw[49 + kh * 7 + kw];
            #pragma unroll
            for (int j = 0; j < 4; j++) {
                float4 m = seg[j + kw];
                y1[j] = fmaf(m.x, w0c, fmaf(m.y, w1c, y1[j]));
                y2[j] = fmaf(m.z, w0c, fmaf(m.w, w1c, y2[j]));
            }
        }
    }

    float scale = rsqrtf(__ldg(var) + 1e-5f) * __ldg(gamma);
    float bias  = __ldg(beta) - __ldg(mean) * scale;
    float a1[4], a2[4];
    #pragma unroll
    for (int j = 0; j < 4; j++) {
        float v1 = fmaxf(fmaf(y1[j], scale, bias), 0.f);
        float v2 = fmaxf(fmaf(y2[j], scale, bias), 0.f);
        a1[j] = 1.0f / (1.0f + expf(-v1));
        a2[j] = 1.0f / (1.0f + expf(-v2));
    }

    // channel loop: out = x * (rel ? A1 : A2), one float4 per channel
    unsigned long long mask = g_mask[b];
    size_t base4 = ((size_t)b * C_ * HW + h * W_ + wb) >> 2;
    const float4* xp = (const float4*)x + base4;
    float4* op = (float4*)out + base4;

    #pragma unroll 8
    for (int c = 0; c < C_; c++) {
        bool rel = (mask >> c) & 1ull;
        float4 v = __ldg(xp + c * (HW / 4));
        float4 r;
        r.x = v.x * (rel ? a1[0] : a2[0]);
        r.y = v.y * (rel ? a1[1] : a2[1]);
        r.z = v.z * (rel ? a1[2] : a2[2]);
        r.w = v.w * (rel ? a1[3] : a2[3]);
        op[c * (HW / 4)] = r;
    }
}

// ---------------------------------------------------------------------------
extern "C" void kernel_launch(void* const* d_in, const int* in_sizes, int n_in,
                              void* d_out, int out_size) {
    const float* x     = (const float*)d_in[0];
    const float* M     = (const float*)d_in[1];
    const float* cw    = (const float*)d_in[2];
    const float* gamma = (const float*)d_in[3];
    const float* beta  = (const float*)d_in[4];
    const float* mean  = (const float*)d_in[5];
    const float* var   = (const float*)d_in[6];
    float* out = (float*)d_out;

    reduce_kernel<<<B_ * 16, 256>>>(x, M);          // 512 CTAs
    fused_kernel <<<B_ * 16, 256>>>(x, out, cw, gamma, beta, mean, var);
}